// round 1
// baseline (speedup 1.0000x reference)
#include <cuda_runtime.h>
#include <math.h>

// Problem constants
#define Dd    2048
#define NTOK  4096      // B*S
#define Sq    1024
#define HDh   64
#define NBH   128       // B*H
#define EPSV  1e-5f
#define INV_SQRT_D 0.022097086912079608f   // 1/sqrt(2048)

// Scratch (device globals; allocation is forbidden)
__device__ float g_h [(size_t)NTOK * Dd];
__device__ float g_x2[(size_t)NTOK * Dd];
__device__ float g_h2[(size_t)NTOK * Dd];
__device__ float g_q [(size_t)NTOK * Dd];
__device__ float g_k [(size_t)NTOK * Dd];
__device__ float g_f1[(size_t)NTOK * Dd];

// ---------------------------------------------------------------------------
// Fused LN1 -> h, x2 = h + x, LN2(x2) -> h2.   One block per token row.
// ---------------------------------------------------------------------------
__global__ __launch_bounds__(256) void ln_fused(
    const float* __restrict__ x,
    const float* __restrict__ s1, const float* __restrict__ b1,
    const float* __restrict__ s2, const float* __restrict__ b2)
{
    __shared__ float rbuf[16];
    __shared__ float stats[2];
    const int tid = threadIdx.x;
    const size_t base = (size_t)blockIdx.x * Dd;
    const float4* xr = (const float4*)(x + base);
    float4 a0 = xr[tid];
    float4 a1 = xr[tid + 256];

    float s = a0.x + a0.y + a0.z + a0.w + a1.x + a1.y + a1.z + a1.w;
    float q = a0.x*a0.x + a0.y*a0.y + a0.z*a0.z + a0.w*a0.w
            + a1.x*a1.x + a1.y*a1.y + a1.z*a1.z + a1.w*a1.w;
    #pragma unroll
    for (int o = 16; o; o >>= 1) {
        s += __shfl_xor_sync(0xffffffffu, s, o);
        q += __shfl_xor_sync(0xffffffffu, q, o);
    }
    if ((tid & 31) == 0) { rbuf[tid >> 5] = s; rbuf[8 + (tid >> 5)] = q; }
    __syncthreads();
    if (tid == 0) {
        float ss = 0.f, qq = 0.f;
        #pragma unroll
        for (int i = 0; i < 8; i++) { ss += rbuf[i]; qq += rbuf[8 + i]; }
        float m = ss * (1.0f / Dd);
        stats[0] = m;
        stats[1] = rsqrtf(qq * (1.0f / Dd) - m * m + EPSV);
    }
    __syncthreads();
    float m = stats[0], r = stats[1];

    const float4* s1v = (const float4*)s1;
    const float4* b1v = (const float4*)b1;
    float4 sc0 = s1v[tid], sc1 = s1v[tid + 256];
    float4 bi0 = b1v[tid], bi1 = b1v[tid + 256];

    float4 h0, h1, x20, x21;
    h0.x = (a0.x - m) * r * sc0.x + bi0.x;  h0.y = (a0.y - m) * r * sc0.y + bi0.y;
    h0.z = (a0.z - m) * r * sc0.z + bi0.z;  h0.w = (a0.w - m) * r * sc0.w + bi0.w;
    h1.x = (a1.x - m) * r * sc1.x + bi1.x;  h1.y = (a1.y - m) * r * sc1.y + bi1.y;
    h1.z = (a1.z - m) * r * sc1.z + bi1.z;  h1.w = (a1.w - m) * r * sc1.w + bi1.w;
    x20.x = h0.x + a0.x; x20.y = h0.y + a0.y; x20.z = h0.z + a0.z; x20.w = h0.w + a0.w;
    x21.x = h1.x + a1.x; x21.y = h1.y + a1.y; x21.z = h1.z + a1.z; x21.w = h1.w + a1.w;

    ((float4*)(g_h  + base))[tid]       = h0;
    ((float4*)(g_h  + base))[tid + 256] = h1;
    ((float4*)(g_x2 + base))[tid]       = x20;
    ((float4*)(g_x2 + base))[tid + 256] = x21;

    // LN2 over x2
    s = x20.x + x20.y + x20.z + x20.w + x21.x + x21.y + x21.z + x21.w;
    q = x20.x*x20.x + x20.y*x20.y + x20.z*x20.z + x20.w*x20.w
      + x21.x*x21.x + x21.y*x21.y + x21.z*x21.z + x21.w*x21.w;
    #pragma unroll
    for (int o = 16; o; o >>= 1) {
        s += __shfl_xor_sync(0xffffffffu, s, o);
        q += __shfl_xor_sync(0xffffffffu, q, o);
    }
    if ((tid & 31) == 0) { rbuf[tid >> 5] = s; rbuf[8 + (tid >> 5)] = q; }
    __syncthreads();
    if (tid == 0) {
        float ss = 0.f, qq = 0.f;
        #pragma unroll
        for (int i = 0; i < 8; i++) { ss += rbuf[i]; qq += rbuf[8 + i]; }
        float mm = ss * (1.0f / Dd);
        stats[0] = mm;
        stats[1] = rsqrtf(qq * (1.0f / Dd) - mm * mm + EPSV);
    }
    __syncthreads();
    m = stats[0]; r = stats[1];

    const float4* s2v = (const float4*)s2;
    const float4* b2v = (const float4*)b2;
    sc0 = s2v[tid]; sc1 = s2v[tid + 256];
    bi0 = b2v[tid]; bi1 = b2v[tid + 256];
    float4 o0, o1;
    o0.x = (x20.x - m) * r * sc0.x + bi0.x;  o0.y = (x20.y - m) * r * sc0.y + bi0.y;
    o0.z = (x20.z - m) * r * sc0.z + bi0.z;  o0.w = (x20.w - m) * r * sc0.w + bi0.w;
    o1.x = (x21.x - m) * r * sc1.x + bi1.x;  o1.y = (x21.y - m) * r * sc1.y + bi1.y;
    o1.z = (x21.z - m) * r * sc1.z + bi1.z;  o1.w = (x21.w - m) * r * sc1.w + bi1.w;
    ((float4*)(g_h2 + base))[tid]       = o0;
    ((float4*)(g_h2 + base))[tid + 256] = o1;
}

// ---------------------------------------------------------------------------
// Tiled fp32 GEMM.  C[M,N] = A[M,K] * B[K,N]  (or A * B^T when TRANSB).
// 128x128 block tile, BK=16, 256 threads, 8x8 per-thread microtile.
// EPI: 0 = plain store, 1 = relu(acc + bias[n]), 2 = acc + bias[n] + add[m,n]
// TRANSB also implies the batched attention-score addressing (blockIdx.z = bh).
// ---------------------------------------------------------------------------
template<bool TRANSB, int EPI>
__global__ __launch_bounds__(256) void sgemm(
    int M, int N, int K,
    const float* __restrict__ A, int lda,
    const float* __restrict__ Bm, int ldb,
    float* __restrict__ C, int ldc,
    const float* __restrict__ bias,
    const float* __restrict__ addm)
{
    if (TRANSB) {
        size_t off = (size_t)(blockIdx.z >> 5) * ((size_t)Sq * Dd)
                   + (size_t)(blockIdx.z & 31) * HDh;
        A  += off;
        Bm += off;
        C  += (size_t)blockIdx.z * Sq * Sq;
    }
    __shared__ float As[16][128];
    __shared__ float Bs[16][132];

    const int tid = threadIdx.x;
    const int tx = tid & 15;
    const int ty = tid >> 4;
    const int ar = tid >> 2;
    const int ac = (tid & 3) << 2;
    const int br = tid >> 5;
    const int bc = (tid & 31) << 2;
    const int rowA0 = blockIdx.y * 128 + ar;
    const int colB0 = blockIdx.x * 128;

    float acc[8][8];
    #pragma unroll
    for (int i = 0; i < 8; i++)
        #pragma unroll
        for (int j = 0; j < 8; j++) acc[i][j] = 0.f;

    for (int k0 = 0; k0 < K; k0 += 16) {
        float4 a0 = *(const float4*)(A + (size_t)rowA0 * lda + k0 + ac);
        float4 a1 = *(const float4*)(A + (size_t)(rowA0 + 64) * lda + k0 + ac);
        float4 b0, b1;
        if (TRANSB) {
            b0 = *(const float4*)(Bm + (size_t)(colB0 + ar) * ldb + k0 + ac);
            b1 = *(const float4*)(Bm + (size_t)(colB0 + ar + 64) * ldb + k0 + ac);
        } else {
            b0 = *(const float4*)(Bm + (size_t)(k0 + br) * ldb + colB0 + bc);
            b1 = *(const float4*)(Bm + (size_t)(k0 + br + 8) * ldb + colB0 + bc);
        }
        __syncthreads();
        As[ac + 0][ar] = a0.x; As[ac + 1][ar] = a0.y;
        As[ac + 2][ar] = a0.z; As[ac + 3][ar] = a0.w;
        As[ac + 0][ar + 64] = a1.x; As[ac + 1][ar + 64] = a1.y;
        As[ac + 2][ar + 64] = a1.z; As[ac + 3][ar + 64] = a1.w;
        if (TRANSB) {
            Bs[ac + 0][ar] = b0.x; Bs[ac + 1][ar] = b0.y;
            Bs[ac + 2][ar] = b0.z; Bs[ac + 3][ar] = b0.w;
            Bs[ac + 0][ar + 64] = b1.x; Bs[ac + 1][ar + 64] = b1.y;
            Bs[ac + 2][ar + 64] = b1.z; Bs[ac + 3][ar + 64] = b1.w;
        } else {
            *(float4*)&Bs[br][bc]     = b0;
            *(float4*)&Bs[br + 8][bc] = b1;
        }
        __syncthreads();

        #pragma unroll
        for (int kk = 0; kk < 16; kk++) {
            float4 ra0 = *(const float4*)&As[kk][ty * 8];
            float4 ra1 = *(const float4*)&As[kk][ty * 8 + 4];
            float4 rb0 = *(const float4*)&Bs[kk][tx * 8];
            float4 rb1 = *(const float4*)&Bs[kk][tx * 8 + 4];
            float ra[8] = {ra0.x, ra0.y, ra0.z, ra0.w, ra1.x, ra1.y, ra1.z, ra1.w};
            float rb[8] = {rb0.x, rb0.y, rb0.z, rb0.w, rb1.x, rb1.y, rb1.z, rb1.w};
            #pragma unroll
            for (int i = 0; i < 8; i++)
                #pragma unroll
                for (int j = 0; j < 8; j++)
                    acc[i][j] += ra[i] * rb[j];
        }
    }

    const int row0 = blockIdx.y * 128 + ty * 8;
    const int col0 = blockIdx.x * 128 + tx * 8;
    float4 bia0, bia1;
    if (EPI >= 1) {
        bia0 = *(const float4*)(bias + col0);
        bia1 = *(const float4*)(bias + col0 + 4);
    }
    #pragma unroll
    for (int i = 0; i < 8; i++) {
        const int row = row0 + i;
        float4 v0 = make_float4(acc[i][0], acc[i][1], acc[i][2], acc[i][3]);
        float4 v1 = make_float4(acc[i][4], acc[i][5], acc[i][6], acc[i][7]);
        if (EPI == 1) {
            v0.x = fmaxf(v0.x + bia0.x, 0.f); v0.y = fmaxf(v0.y + bia0.y, 0.f);
            v0.z = fmaxf(v0.z + bia0.z, 0.f); v0.w = fmaxf(v0.w + bia0.w, 0.f);
            v1.x = fmaxf(v1.x + bia1.x, 0.f); v1.y = fmaxf(v1.y + bia1.y, 0.f);
            v1.z = fmaxf(v1.z + bia1.z, 0.f); v1.w = fmaxf(v1.w + bia1.w, 0.f);
        } else if (EPI == 2) {
            float4 ad0 = *(const float4*)(addm + (size_t)row * ldc + col0);
            float4 ad1 = *(const float4*)(addm + (size_t)row * ldc + col0 + 4);
            v0.x += bia0.x + ad0.x; v0.y += bia0.y + ad0.y;
            v0.z += bia0.z + ad0.z; v0.w += bia0.w + ad0.w;
            v1.x += bia1.x + ad1.x; v1.y += bia1.y + ad1.y;
            v1.z += bia1.z + ad1.z; v1.w += bia1.w + ad1.w;
        }
        *(float4*)(C + (size_t)row * ldc + col0)     = v0;
        *(float4*)(C + (size_t)row * ldc + col0 + 4) = v1;
    }
}

// ---------------------------------------------------------------------------
// In-place row softmax over scaled scores.  One block per row of 1024.
// ---------------------------------------------------------------------------
__global__ __launch_bounds__(128) void softmax_rows(float* __restrict__ attn)
{
    __shared__ float rbuf[4];
    const int tid = threadIdx.x;
    float4* pr = (float4*)(attn + (size_t)blockIdx.x * 1024);
    float4 a = pr[tid];
    float4 b = pr[tid + 128];
    const float c = INV_SQRT_D;
    a.x *= c; a.y *= c; a.z *= c; a.w *= c;
    b.x *= c; b.y *= c; b.z *= c; b.w *= c;

    float mx = fmaxf(fmaxf(fmaxf(a.x, a.y), fmaxf(a.z, a.w)),
                     fmaxf(fmaxf(b.x, b.y), fmaxf(b.z, b.w)));
    #pragma unroll
    for (int o = 16; o; o >>= 1) mx = fmaxf(mx, __shfl_xor_sync(0xffffffffu, mx, o));
    if ((tid & 31) == 0) rbuf[tid >> 5] = mx;
    __syncthreads();
    mx = fmaxf(fmaxf(rbuf[0], rbuf[1]), fmaxf(rbuf[2], rbuf[3]));

    a.x = __expf(a.x - mx); a.y = __expf(a.y - mx);
    a.z = __expf(a.z - mx); a.w = __expf(a.w - mx);
    b.x = __expf(b.x - mx); b.y = __expf(b.y - mx);
    b.z = __expf(b.z - mx); b.w = __expf(b.w - mx);

    float sm = a.x + a.y + a.z + a.w + b.x + b.y + b.z + b.w;
    #pragma unroll
    for (int o = 16; o; o >>= 1) sm += __shfl_xor_sync(0xffffffffu, sm, o);
    __syncthreads();                       // rbuf reuse
    if ((tid & 31) == 0) rbuf[tid >> 5] = sm;
    __syncthreads();
    sm = rbuf[0] + rbuf[1] + rbuf[2] + rbuf[3];
    const float inv = __fdividef(1.0f, sm);

    a.x *= inv; a.y *= inv; a.z *= inv; a.w *= inv;
    b.x *= inv; b.y *= inv; b.z *= inv; b.w *= inv;
    pr[tid] = a;
    pr[tid + 128] = b;
}

// ---------------------------------------------------------------------------
extern "C" void kernel_launch(void* const* d_in, const int* in_sizes, int n_in,
                              void* d_out, int out_size)
{
    (void)in_sizes; (void)n_in; (void)out_size;
    const float* x    = (const float*)d_in[0];
    const float* Wq   = (const float*)d_in[1];
    const float* Wk   = (const float*)d_in[2];
    /* d_in[3] = Wv : dead in the reference (attended values never used) */
    const float* ln1s = (const float*)d_in[4];
    const float* ln1b = (const float*)d_in[5];
    const float* ln2s = (const float*)d_in[6];
    const float* ln2b = (const float*)d_in[7];
    const float* ff1w = (const float*)d_in[8];
    const float* ff1b = (const float*)d_in[9];
    const float* ff2w = (const float*)d_in[10];
    const float* ff2b = (const float*)d_in[11];

    float* out  = (float*)d_out;                      // [4,1024,2048]
    float* attn = out + (size_t)NTOK * Dd;            // [4,32,1024,1024]

    float *ph, *px2, *ph2, *pq, *pk, *pf1;
    cudaGetSymbolAddress((void**)&ph,  g_h);
    cudaGetSymbolAddress((void**)&px2, g_x2);
    cudaGetSymbolAddress((void**)&ph2, g_h2);
    cudaGetSymbolAddress((void**)&pq,  g_q);
    cudaGetSymbolAddress((void**)&pk,  g_k);
    cudaGetSymbolAddress((void**)&pf1, g_f1);

    // 1) fused LayerNorms + residual
    ln_fused<<<NTOK, 256>>>(x, ln1s, ln1b, ln2s, ln2b);

    // 2) projections q = h*Wq, k = h*Wk
    dim3 g0(Dd / 128, NTOK / 128, 1);
    sgemm<false, 0><<<g0, 256>>>(NTOK, Dd, Dd, ph, Dd, Wq, Dd, pq, Dd, nullptr, nullptr);
    sgemm<false, 0><<<g0, 256>>>(NTOK, Dd, Dd, ph, Dd, Wk, Dd, pk, Dd, nullptr, nullptr);

    // 3) FFN: f1 = relu(h2*W1 + b1);  out = f1*W2 + b2 + x2
    sgemm<false, 1><<<g0, 256>>>(NTOK, Dd, Dd, ph2, Dd, ff1w, Dd, pf1, Dd, ff1b, nullptr);
    sgemm<false, 2><<<g0, 256>>>(NTOK, Dd, Dd, pf1, Dd, ff2w, Dd, out, Dd, ff2b, px2);

    // 4) attention scores (batched over 128 bh), written raw into the output buffer
    dim3 gs(Sq / 128, Sq / 128, NBH);
    sgemm<true, 0><<<gs, 256>>>(Sq, Sq, HDh, pq, Dd, pk, Dd, attn, Sq, nullptr, nullptr);

    // 5) in-place softmax with 1/sqrt(D) scaling
    softmax_rows<<<NBH * Sq, 128>>>(attn);
}

// round 2
// speedup vs baseline: 2.4418x; 2.4418x over previous
#include <cuda_runtime.h>
#include <cuda_bf16.h>
#include <cstdint>
#include <math.h>

#define Dd    2048
#define NTOK  4096
#define Sq    1024
#define HDh   64
#define NBH   128
#define EPSV  1e-5f
#define INV_SQRT_D 0.022097086912079608f

// ---------------- scratch (device globals; allocation forbidden) ----------
__device__ float g_x2[(size_t)NTOK * Dd];
__device__ __nv_bfloat16 g_hh [(size_t)NTOK * Dd], g_hl [(size_t)NTOK * Dd];
__device__ __nv_bfloat16 g_h2h[(size_t)NTOK * Dd], g_h2l[(size_t)NTOK * Dd];
__device__ __nv_bfloat16 g_f1h[(size_t)NTOK * Dd], g_f1l[(size_t)NTOK * Dd];
__device__ __nv_bfloat16 g_qh [(size_t)NTOK * Dd], g_ql [(size_t)NTOK * Dd];
__device__ __nv_bfloat16 g_kh [(size_t)NTOK * Dd], g_kl [(size_t)NTOK * Dd];
__device__ __nv_bfloat16 g_wqh[(size_t)Dd * Dd], g_wql[(size_t)Dd * Dd];
__device__ __nv_bfloat16 g_wkh[(size_t)Dd * Dd], g_wkl[(size_t)Dd * Dd];
__device__ __nv_bfloat16 g_w1h[(size_t)Dd * Dd], g_w1l[(size_t)Dd * Dd];
__device__ __nv_bfloat16 g_w2h[(size_t)Dd * Dd], g_w2l[(size_t)Dd * Dd];

// ---------------- small helpers -------------------------------------------
__device__ __forceinline__ uint32_t smem_u32(const void* p) {
    return (uint32_t)__cvta_generic_to_shared(p);
}
__device__ __forceinline__ void ldmx4(uint32_t a, uint32_t& r0, uint32_t& r1,
                                      uint32_t& r2, uint32_t& r3) {
    asm volatile("ldmatrix.sync.aligned.m8n8.x4.shared.b16 {%0,%1,%2,%3},[%4];"
                 : "=r"(r0), "=r"(r1), "=r"(r2), "=r"(r3) : "r"(a));
}
__device__ __forceinline__ void ldmx4t(uint32_t a, uint32_t& r0, uint32_t& r1,
                                       uint32_t& r2, uint32_t& r3) {
    asm volatile("ldmatrix.sync.aligned.m8n8.x4.trans.shared.b16 {%0,%1,%2,%3},[%4];"
                 : "=r"(r0), "=r"(r1), "=r"(r2), "=r"(r3) : "r"(a));
}
__device__ __forceinline__ void mma16816(float* c, const uint32_t* a, const uint32_t* b) {
    asm volatile(
        "mma.sync.aligned.m16n8k16.row.col.f32.bf16.bf16.f32 "
        "{%0,%1,%2,%3},{%4,%5,%6,%7},{%8,%9},{%0,%1,%2,%3};"
        : "+f"(c[0]), "+f"(c[1]), "+f"(c[2]), "+f"(c[3])
        : "r"(a[0]), "r"(a[1]), "r"(a[2]), "r"(a[3]), "r"(b[0]), "r"(b[1]));
}
__device__ __forceinline__ void split2(float v0, float v1,
                                       __nv_bfloat162& hi, __nv_bfloat162& lo) {
    __nv_bfloat16 h0 = __float2bfloat16(v0);
    __nv_bfloat16 h1 = __float2bfloat16(v1);
    __nv_bfloat16 l0 = __float2bfloat16(v0 - __bfloat162float(h0));
    __nv_bfloat16 l1 = __float2bfloat16(v1 - __bfloat162float(h1));
    hi.x = h0; hi.y = h1; lo.x = l0; lo.y = l1;
}
__device__ __forceinline__ void split_store4(__nv_bfloat16* hi, __nv_bfloat16* lo,
                                             size_t idx, float4 v) {
    __nv_bfloat162 h01, l01, h23, l23;
    split2(v.x, v.y, h01, l01);
    split2(v.z, v.w, h23, l23);
    *(__nv_bfloat162*)(hi + idx)     = h01;
    *(__nv_bfloat162*)(hi + idx + 2) = h23;
    *(__nv_bfloat162*)(lo + idx)     = l01;
    *(__nv_bfloat162*)(lo + idx + 2) = l23;
}

// ---------------- weight split --------------------------------------------
__global__ __launch_bounds__(256) void splitf(const float4* __restrict__ W,
                                              __nv_bfloat16* __restrict__ hi,
                                              __nv_bfloat16* __restrict__ lo, int n4) {
    int i = blockIdx.x * 256 + threadIdx.x;
    if (i >= n4) return;
    split_store4(hi, lo, (size_t)i * 4, W[i]);
}

// ---------------- fused LN1 / residual / LN2 ------------------------------
__global__ __launch_bounds__(256) void ln_fused(
    const float* __restrict__ x,
    const float* __restrict__ s1, const float* __restrict__ b1,
    const float* __restrict__ s2, const float* __restrict__ b2)
{
    __shared__ float rbuf[16];
    __shared__ float stats[2];
    const int tid = threadIdx.x;
    const size_t base = (size_t)blockIdx.x * Dd;
    const float4* xr = (const float4*)(x + base);
    float4 a0 = xr[tid];
    float4 a1 = xr[tid + 256];

    float s = a0.x + a0.y + a0.z + a0.w + a1.x + a1.y + a1.z + a1.w;
    float q = a0.x*a0.x + a0.y*a0.y + a0.z*a0.z + a0.w*a0.w
            + a1.x*a1.x + a1.y*a1.y + a1.z*a1.z + a1.w*a1.w;
    #pragma unroll
    for (int o = 16; o; o >>= 1) {
        s += __shfl_xor_sync(0xffffffffu, s, o);
        q += __shfl_xor_sync(0xffffffffu, q, o);
    }
    if ((tid & 31) == 0) { rbuf[tid >> 5] = s; rbuf[8 + (tid >> 5)] = q; }
    __syncthreads();
    if (tid == 0) {
        float ss = 0.f, qq = 0.f;
        #pragma unroll
        for (int i = 0; i < 8; i++) { ss += rbuf[i]; qq += rbuf[8 + i]; }
        float m = ss * (1.0f / Dd);
        stats[0] = m;
        stats[1] = rsqrtf(qq * (1.0f / Dd) - m * m + EPSV);
    }
    __syncthreads();
    float m = stats[0], r = stats[1];

    const float4* s1v = (const float4*)s1;
    const float4* b1v = (const float4*)b1;
    float4 sc0 = s1v[tid], sc1 = s1v[tid + 256];
    float4 bi0 = b1v[tid], bi1 = b1v[tid + 256];

    float4 h0, h1, x20, x21;
    h0.x = (a0.x - m) * r * sc0.x + bi0.x;  h0.y = (a0.y - m) * r * sc0.y + bi0.y;
    h0.z = (a0.z - m) * r * sc0.z + bi0.z;  h0.w = (a0.w - m) * r * sc0.w + bi0.w;
    h1.x = (a1.x - m) * r * sc1.x + bi1.x;  h1.y = (a1.y - m) * r * sc1.y + bi1.y;
    h1.z = (a1.z - m) * r * sc1.z + bi1.z;  h1.w = (a1.w - m) * r * sc1.w + bi1.w;
    x20.x = h0.x + a0.x; x20.y = h0.y + a0.y; x20.z = h0.z + a0.z; x20.w = h0.w + a0.w;
    x21.x = h1.x + a1.x; x21.y = h1.y + a1.y; x21.z = h1.z + a1.z; x21.w = h1.w + a1.w;

    split_store4(g_hh, g_hl, base + (size_t)tid * 4, h0);
    split_store4(g_hh, g_hl, base + (size_t)(tid + 256) * 4, h1);
    ((float4*)(g_x2 + base))[tid]       = x20;
    ((float4*)(g_x2 + base))[tid + 256] = x21;

    s = x20.x + x20.y + x20.z + x20.w + x21.x + x21.y + x21.z + x21.w;
    q = x20.x*x20.x + x20.y*x20.y + x20.z*x20.z + x20.w*x20.w
      + x21.x*x21.x + x21.y*x21.y + x21.z*x21.z + x21.w*x21.w;
    #pragma unroll
    for (int o = 16; o; o >>= 1) {
        s += __shfl_xor_sync(0xffffffffu, s, o);
        q += __shfl_xor_sync(0xffffffffu, q, o);
    }
    if ((tid & 31) == 0) { rbuf[tid >> 5] = s; rbuf[8 + (tid >> 5)] = q; }
    __syncthreads();
    if (tid == 0) {
        float ss = 0.f, qq = 0.f;
        #pragma unroll
        for (int i = 0; i < 8; i++) { ss += rbuf[i]; qq += rbuf[8 + i]; }
        float mm = ss * (1.0f / Dd);
        stats[0] = mm;
        stats[1] = rsqrtf(qq * (1.0f / Dd) - mm * mm + EPSV);
    }
    __syncthreads();
    m = stats[0]; r = stats[1];

    const float4* s2v = (const float4*)s2;
    const float4* b2v = (const float4*)b2;
    sc0 = s2v[tid]; sc1 = s2v[tid + 256];
    bi0 = b2v[tid]; bi1 = b2v[tid + 256];
    float4 o0, o1;
    o0.x = (x20.x - m) * r * sc0.x + bi0.x;  o0.y = (x20.y - m) * r * sc0.y + bi0.y;
    o0.z = (x20.z - m) * r * sc0.z + bi0.z;  o0.w = (x20.w - m) * r * sc0.w + bi0.w;
    o1.x = (x21.x - m) * r * sc1.x + bi1.x;  o1.y = (x21.y - m) * r * sc1.y + bi1.y;
    o1.z = (x21.z - m) * r * sc1.z + bi1.z;  o1.w = (x21.w - m) * r * sc1.w + bi1.w;
    split_store4(g_h2h, g_h2l, base + (size_t)tid * 4, o0);
    split_store4(g_h2h, g_h2l, base + (size_t)(tid + 256) * 4, o1);
}

// ---------------------------------------------------------------------------
// bf16 split-3 GEMM: C = A*B,  A[M,K] k-major (hi/lo), B[K,N] n-major (hi/lo).
// Block 128x128, BK=32(bf16), 256 threads = 8 warps (2Mx4N), warp tile 64x32.
// EPI: 1 = relu(acc+bias) -> split-store bf16 hi/lo
//      2 = acc + bias + addm -> fp32 C
//      3 = split-store bf16 hi/lo (no bias)
// ---------------------------------------------------------------------------
template<int EPI>
__global__ __launch_bounds__(256) void gemm3(
    int M, int N, int K,
    const __nv_bfloat16* __restrict__ Ah, const __nv_bfloat16* __restrict__ Al,
    const __nv_bfloat16* __restrict__ Bh, const __nv_bfloat16* __restrict__ Bl,
    float* __restrict__ C,
    const float* __restrict__ bias, const float* __restrict__ addm,
    __nv_bfloat16* __restrict__ Ohi, __nv_bfloat16* __restrict__ Olo)
{
    __shared__ __nv_bfloat16 sAh[128 * 40], sAl[128 * 40];
    __shared__ __nv_bfloat16 sBh[32 * 136], sBl[32 * 136];

    const int tid = threadIdx.x;
    const int m0 = blockIdx.y * 128, n0 = blockIdx.x * 128;
    const int s0 = tid, s1 = tid + 256;

    // global pointers (A: row-of-K; B: row-of-N)
    const __nv_bfloat16* gAh0 = Ah + (size_t)(m0 + (s0 >> 2)) * K + (s0 & 3) * 8;
    const __nv_bfloat16* gAh1 = Ah + (size_t)(m0 + (s1 >> 2)) * K + (s1 & 3) * 8;
    const __nv_bfloat16* gAl0 = Al + (size_t)(m0 + (s0 >> 2)) * K + (s0 & 3) * 8;
    const __nv_bfloat16* gAl1 = Al + (size_t)(m0 + (s1 >> 2)) * K + (s1 & 3) * 8;
    const __nv_bfloat16* gBh0 = Bh + (size_t)(s0 >> 4) * N + n0 + (s0 & 15) * 8;
    const __nv_bfloat16* gBh1 = Bh + (size_t)(s1 >> 4) * N + n0 + (s1 & 15) * 8;
    const __nv_bfloat16* gBl0 = Bl + (size_t)(s0 >> 4) * N + n0 + (s0 & 15) * 8;
    const __nv_bfloat16* gBl1 = Bl + (size_t)(s1 >> 4) * N + n0 + (s1 & 15) * 8;

    const int sa0 = (s0 >> 2) * 40 + (s0 & 3) * 8;
    const int sa1 = (s1 >> 2) * 40 + (s1 & 3) * 8;
    const int sb0 = (s0 >> 4) * 136 + (s0 & 15) * 8;
    const int sb1 = (s1 >> 4) * 136 + (s1 & 15) * 8;

    const int lane = tid & 31;
    const int wid = tid >> 5;
    const int wm = (wid & 1) * 64;
    const int wn = (wid >> 1) * 32;

    const uint32_t aBaseH = smem_u32(sAh) + (((wm + (lane & 15)) * 40 + ((lane >> 4) << 3)) << 1);
    const uint32_t aBaseL = smem_u32(sAl) + (((wm + (lane & 15)) * 40 + ((lane >> 4) << 3)) << 1);
    const uint32_t bBaseH = smem_u32(sBh) + ((((lane & 15)) * 136 + wn + ((lane >> 4) << 3)) << 1);
    const uint32_t bBaseL = smem_u32(sBl) + ((((lane & 15)) * 136 + wn + ((lane >> 4) << 3)) << 1);

    float acc[4][4][4];
    #pragma unroll
    for (int i = 0; i < 4; i++)
        #pragma unroll
        for (int j = 0; j < 4; j++)
            #pragma unroll
            for (int t = 0; t < 4; t++) acc[i][j][t] = 0.f;

    uint4 vah0, vah1, val0, val1, vbh0, vbh1, vbl0, vbl1;

    auto LDG = [&](int k0) {
        vah0 = *(const uint4*)(gAh0 + k0);
        vah1 = *(const uint4*)(gAh1 + k0);
        val0 = *(const uint4*)(gAl0 + k0);
        val1 = *(const uint4*)(gAl1 + k0);
        vbh0 = *(const uint4*)(gBh0 + (size_t)k0 * N);
        vbh1 = *(const uint4*)(gBh1 + (size_t)k0 * N);
        vbl0 = *(const uint4*)(gBl0 + (size_t)k0 * N);
        vbl1 = *(const uint4*)(gBl1 + (size_t)k0 * N);
    };
    auto STS = [&]() {
        *(uint4*)(sAh + sa0) = vah0;  *(uint4*)(sAh + sa1) = vah1;
        *(uint4*)(sAl + sa0) = val0;  *(uint4*)(sAl + sa1) = val1;
        *(uint4*)(sBh + sb0) = vbh0;  *(uint4*)(sBh + sb1) = vbh1;
        *(uint4*)(sBl + sb0) = vbl0;  *(uint4*)(sBl + sb1) = vbl1;
    };
    auto COMP = [&](int kb) {
        uint32_t afh[4][4], afl[4][4], bfh[4][2], bfl[4][2];
        #pragma unroll
        for (int mt = 0; mt < 4; mt++) {
            ldmx4(aBaseH + ((mt * 16 * 40 + kb) << 1),
                  afh[mt][0], afh[mt][1], afh[mt][2], afh[mt][3]);
            ldmx4(aBaseL + ((mt * 16 * 40 + kb) << 1),
                  afl[mt][0], afl[mt][1], afl[mt][2], afl[mt][3]);
        }
        #pragma unroll
        for (int np = 0; np < 2; np++) {
            ldmx4t(bBaseH + ((kb * 136 + np * 16) << 1),
                   bfh[2*np][0], bfh[2*np][1], bfh[2*np+1][0], bfh[2*np+1][1]);
            ldmx4t(bBaseL + ((kb * 136 + np * 16) << 1),
                   bfl[2*np][0], bfl[2*np][1], bfl[2*np+1][0], bfl[2*np+1][1]);
        }
        #pragma unroll
        for (int mt = 0; mt < 4; mt++)
            #pragma unroll
            for (int nt = 0; nt < 4; nt++) {
                mma16816(acc[mt][nt], afh[mt], bfh[nt]);
                mma16816(acc[mt][nt], afh[mt], bfl[nt]);
                mma16816(acc[mt][nt], afl[mt], bfh[nt]);
            }
    };

    LDG(0);
    STS();
    __syncthreads();
    for (int k0 = 32; k0 < K; k0 += 32) {
        LDG(k0);
        COMP(0);
        COMP(16);
        __syncthreads();
        STS();
        __syncthreads();
    }
    COMP(0);
    COMP(16);

    // epilogue
    const int g = lane >> 2, tig = lane & 3;
    #pragma unroll
    for (int mt = 0; mt < 4; mt++) {
        #pragma unroll
        for (int nt = 0; nt < 4; nt++) {
            const int row = m0 + wm + mt * 16 + g;
            const int col = n0 + wn + nt * 8 + tig * 2;
            const float* a4 = acc[mt][nt];
            if (EPI == 3) {
                __nv_bfloat162 h01, l01, h23, l23;
                split2(a4[0], a4[1], h01, l01);
                split2(a4[2], a4[3], h23, l23);
                *(__nv_bfloat162*)(Ohi + (size_t)row * N + col)       = h01;
                *(__nv_bfloat162*)(Olo + (size_t)row * N + col)       = l01;
                *(__nv_bfloat162*)(Ohi + (size_t)(row + 8) * N + col) = h23;
                *(__nv_bfloat162*)(Olo + (size_t)(row + 8) * N + col) = l23;
            } else if (EPI == 1) {
                float b0 = bias[col], b1 = bias[col + 1];
                float v0 = fmaxf(a4[0] + b0, 0.f), v1 = fmaxf(a4[1] + b1, 0.f);
                float v2 = fmaxf(a4[2] + b0, 0.f), v3 = fmaxf(a4[3] + b1, 0.f);
                __nv_bfloat162 h01, l01, h23, l23;
                split2(v0, v1, h01, l01);
                split2(v2, v3, h23, l23);
                *(__nv_bfloat162*)(Ohi + (size_t)row * N + col)       = h01;
                *(__nv_bfloat162*)(Olo + (size_t)row * N + col)       = l01;
                *(__nv_bfloat162*)(Ohi + (size_t)(row + 8) * N + col) = h23;
                *(__nv_bfloat162*)(Olo + (size_t)(row + 8) * N + col) = l23;
            } else { // EPI == 2
                float b0 = bias[col], b1 = bias[col + 1];
                float2 ad0 = *(const float2*)(addm + (size_t)row * N + col);
                float2 ad1 = *(const float2*)(addm + (size_t)(row + 8) * N + col);
                float2 o0 = make_float2(a4[0] + b0 + ad0.x, a4[1] + b1 + ad0.y);
                float2 o1 = make_float2(a4[2] + b0 + ad1.x, a4[3] + b1 + ad1.y);
                *(float2*)(C + (size_t)row * N + col)       = o0;
                *(float2*)(C + (size_t)(row + 8) * N + col) = o1;
            }
        }
    }
}

// ---------------------------------------------------------------------------
// Attention scores, batched over 128 (b,h): S = Q_bh * K_bh^T, both k-major.
// Both operands load like "A" tiles; B fragments use NON-trans ldmatrix.
// ---------------------------------------------------------------------------
__global__ __launch_bounds__(256) void scores_mma(
    const __nv_bfloat16* __restrict__ Qh, const __nv_bfloat16* __restrict__ Ql,
    const __nv_bfloat16* __restrict__ Kh, const __nv_bfloat16* __restrict__ Kl,
    float* __restrict__ attn)
{
    __shared__ __nv_bfloat16 sAh[128 * 40], sAl[128 * 40];
    __shared__ __nv_bfloat16 sBh[128 * 40], sBl[128 * 40];

    const int tid = threadIdx.x;
    const int bh = blockIdx.z;
    const size_t off = (size_t)(bh >> 5) * ((size_t)Sq * Dd) + (size_t)(bh & 31) * HDh;
    const int m0 = blockIdx.y * 128, n0 = blockIdx.x * 128;
    const int s0 = tid, s1 = tid + 256;

    const __nv_bfloat16* gAh0 = Qh + off + (size_t)(m0 + (s0 >> 2)) * Dd + (s0 & 3) * 8;
    const __nv_bfloat16* gAh1 = Qh + off + (size_t)(m0 + (s1 >> 2)) * Dd + (s1 & 3) * 8;
    const __nv_bfloat16* gAl0 = Ql + off + (size_t)(m0 + (s0 >> 2)) * Dd + (s0 & 3) * 8;
    const __nv_bfloat16* gAl1 = Ql + off + (size_t)(m0 + (s1 >> 2)) * Dd + (s1 & 3) * 8;
    const __nv_bfloat16* gBh0 = Kh + off + (size_t)(n0 + (s0 >> 2)) * Dd + (s0 & 3) * 8;
    const __nv_bfloat16* gBh1 = Kh + off + (size_t)(n0 + (s1 >> 2)) * Dd + (s1 & 3) * 8;
    const __nv_bfloat16* gBl0 = Kl + off + (size_t)(n0 + (s0 >> 2)) * Dd + (s0 & 3) * 8;
    const __nv_bfloat16* gBl1 = Kl + off + (size_t)(n0 + (s1 >> 2)) * Dd + (s1 & 3) * 8;

    const int sa0 = (s0 >> 2) * 40 + (s0 & 3) * 8;
    const int sa1 = (s1 >> 2) * 40 + (s1 & 3) * 8;

    const int lane = tid & 31;
    const int wid = tid >> 5;
    const int wm = (wid & 1) * 64;
    const int wn = (wid >> 1) * 32;

    const uint32_t aBaseH = smem_u32(sAh) + (((wm + (lane & 15)) * 40 + ((lane >> 4) << 3)) << 1);
    const uint32_t aBaseL = smem_u32(sAl) + (((wm + (lane & 15)) * 40 + ((lane >> 4) << 3)) << 1);
    // B non-trans ldmatrix lane mapping: row = ((lane>>4)<<3)+(lane&7), kof = ((lane>>3)&1)<<3
    const int bRow = ((lane >> 4) << 3) + (lane & 7);
    const int bKof = ((lane >> 3) & 1) << 3;
    const uint32_t bBaseH = smem_u32(sBh) + (((wn + bRow) * 40 + bKof) << 1);
    const uint32_t bBaseL = smem_u32(sBl) + (((wn + bRow) * 40 + bKof) << 1);

    float acc[4][4][4];
    #pragma unroll
    for (int i = 0; i < 4; i++)
        #pragma unroll
        for (int j = 0; j < 4; j++)
            #pragma unroll
            for (int t = 0; t < 4; t++) acc[i][j][t] = 0.f;

    uint4 vah0, vah1, val0, val1, vbh0, vbh1, vbl0, vbl1;
    auto LDG = [&](int k0) {
        vah0 = *(const uint4*)(gAh0 + k0);
        vah1 = *(const uint4*)(gAh1 + k0);
        val0 = *(const uint4*)(gAl0 + k0);
        val1 = *(const uint4*)(gAl1 + k0);
        vbh0 = *(const uint4*)(gBh0 + k0);
        vbh1 = *(const uint4*)(gBh1 + k0);
        vbl0 = *(const uint4*)(gBl0 + k0);
        vbl1 = *(const uint4*)(gBl1 + k0);
    };
    auto STS = [&]() {
        *(uint4*)(sAh + sa0) = vah0;  *(uint4*)(sAh + sa1) = vah1;
        *(uint4*)(sAl + sa0) = val0;  *(uint4*)(sAl + sa1) = val1;
        *(uint4*)(sBh + sa0) = vbh0;  *(uint4*)(sBh + sa1) = vbh1;
        *(uint4*)(sBl + sa0) = vbl0;  *(uint4*)(sBl + sa1) = vbl1;
    };
    auto COMP = [&](int kb) {
        uint32_t afh[4][4], afl[4][4], bfh[4][2], bfl[4][2];
        #pragma unroll
        for (int mt = 0; mt < 4; mt++) {
            ldmx4(aBaseH + ((mt * 16 * 40 + kb) << 1),
                  afh[mt][0], afh[mt][1], afh[mt][2], afh[mt][3]);
            ldmx4(aBaseL + ((mt * 16 * 40 + kb) << 1),
                  afl[mt][0], afl[mt][1], afl[mt][2], afl[mt][3]);
        }
        #pragma unroll
        for (int np = 0; np < 2; np++) {
            ldmx4(bBaseH + ((np * 16 * 40 + kb) << 1),
                  bfh[2*np][0], bfh[2*np][1], bfh[2*np+1][0], bfh[2*np+1][1]);
            ldmx4(bBaseL + ((np * 16 * 40 + kb) << 1),
                  bfl[2*np][0], bfl[2*np][1], bfl[2*np+1][0], bfl[2*np+1][1]);
        }
        #pragma unroll
        for (int mt = 0; mt < 4; mt++)
            #pragma unroll
            for (int nt = 0; nt < 4; nt++) {
                mma16816(acc[mt][nt], afh[mt], bfh[nt]);
                mma16816(acc[mt][nt], afh[mt], bfl[nt]);
                mma16816(acc[mt][nt], afl[mt], bfh[nt]);
            }
    };

    // K = 64 -> two BK=32 tiles
    LDG(0);
    STS();
    __syncthreads();
    LDG(32);
    COMP(0);
    COMP(16);
    __syncthreads();
    STS();
    __syncthreads();
    COMP(0);
    COMP(16);

    float* Cb = attn + (size_t)bh * Sq * Sq;
    const int g = lane >> 2, tig = lane & 3;
    #pragma unroll
    for (int mt = 0; mt < 4; mt++) {
        #pragma unroll
        for (int nt = 0; nt < 4; nt++) {
            const int row = m0 + wm + mt * 16 + g;
            const int col = n0 + wn + nt * 8 + tig * 2;
            const float* a4 = acc[mt][nt];
            *(float2*)(Cb + (size_t)row * Sq + col)       = make_float2(a4[0], a4[1]);
            *(float2*)(Cb + (size_t)(row + 8) * Sq + col) = make_float2(a4[2], a4[3]);
        }
    }
}

// ---------------- softmax ---------------------------------------------------
__global__ __launch_bounds__(128) void softmax_rows(float* __restrict__ attn)
{
    __shared__ float rbuf[4];
    const int tid = threadIdx.x;
    float4* pr = (float4*)(attn + (size_t)blockIdx.x * 1024);
    float4 a = pr[tid];
    float4 b = pr[tid + 128];
    const float c = INV_SQRT_D;
    a.x *= c; a.y *= c; a.z *= c; a.w *= c;
    b.x *= c; b.y *= c; b.z *= c; b.w *= c;

    float mx = fmaxf(fmaxf(fmaxf(a.x, a.y), fmaxf(a.z, a.w)),
                     fmaxf(fmaxf(b.x, b.y), fmaxf(b.z, b.w)));
    #pragma unroll
    for (int o = 16; o; o >>= 1) mx = fmaxf(mx, __shfl_xor_sync(0xffffffffu, mx, o));
    if ((tid & 31) == 0) rbuf[tid >> 5] = mx;
    __syncthreads();
    mx = fmaxf(fmaxf(rbuf[0], rbuf[1]), fmaxf(rbuf[2], rbuf[3]));

    a.x = __expf(a.x - mx); a.y = __expf(a.y - mx);
    a.z = __expf(a.z - mx); a.w = __expf(a.w - mx);
    b.x = __expf(b.x - mx); b.y = __expf(b.y - mx);
    b.z = __expf(b.z - mx); b.w = __expf(b.w - mx);

    float sm = a.x + a.y + a.z + a.w + b.x + b.y + b.z + b.w;
    #pragma unroll
    for (int o = 16; o; o >>= 1) sm += __shfl_xor_sync(0xffffffffu, sm, o);
    __syncthreads();
    if ((tid & 31) == 0) rbuf[tid >> 5] = sm;
    __syncthreads();
    sm = rbuf[0] + rbuf[1] + rbuf[2] + rbuf[3];
    const float inv = __fdividef(1.0f, sm);

    a.x *= inv; a.y *= inv; a.z *= inv; a.w *= inv;
    b.x *= inv; b.y *= inv; b.z *= inv; b.w *= inv;
    pr[tid] = a;
    pr[tid + 128] = b;
}

// ---------------------------------------------------------------------------
extern "C" void kernel_launch(void* const* d_in, const int* in_sizes, int n_in,
                              void* d_out, int out_size)
{
    (void)in_sizes; (void)n_in; (void)out_size;
    const float* x    = (const float*)d_in[0];
    const float* Wq   = (const float*)d_in[1];
    const float* Wk   = (const float*)d_in[2];
    /* d_in[3] = Wv : dead in the reference */
    const float* ln1s = (const float*)d_in[4];
    const float* ln1b = (const float*)d_in[5];
    const float* ln2s = (const float*)d_in[6];
    const float* ln2b = (const float*)d_in[7];
    const float* ff1w = (const float*)d_in[8];
    const float* ff1b = (const float*)d_in[9];
    const float* ff2w = (const float*)d_in[10];
    const float* ff2b = (const float*)d_in[11];

    float* out  = (float*)d_out;
    float* attn = out + (size_t)NTOK * Dd;

    float* px2;
    __nv_bfloat16 *phh, *phl, *ph2h, *ph2l, *pf1h, *pf1l, *pqh, *pql, *pkh, *pkl;
    __nv_bfloat16 *pwqh, *pwql, *pwkh, *pwkl, *pw1h, *pw1l, *pw2h, *pw2l;
    cudaGetSymbolAddress((void**)&px2,  g_x2);
    cudaGetSymbolAddress((void**)&phh,  g_hh);
    cudaGetSymbolAddress((void**)&phl,  g_hl);
    cudaGetSymbolAddress((void**)&ph2h, g_h2h);
    cudaGetSymbolAddress((void**)&ph2l, g_h2l);
    cudaGetSymbolAddress((void**)&pf1h, g_f1h);
    cudaGetSymbolAddress((void**)&pf1l, g_f1l);
    cudaGetSymbolAddress((void**)&pqh,  g_qh);
    cudaGetSymbolAddress((void**)&pql,  g_ql);
    cudaGetSymbolAddress((void**)&pkh,  g_kh);
    cudaGetSymbolAddress((void**)&pkl,  g_kl);
    cudaGetSymbolAddress((void**)&pwqh, g_wqh);
    cudaGetSymbolAddress((void**)&pwql, g_wql);
    cudaGetSymbolAddress((void**)&pwkh, g_wkh);
    cudaGetSymbolAddress((void**)&pwkl, g_wkl);
    cudaGetSymbolAddress((void**)&pw1h, g_w1h);
    cudaGetSymbolAddress((void**)&pw1l, g_w1l);
    cudaGetSymbolAddress((void**)&pw2h, g_w2h);
    cudaGetSymbolAddress((void**)&pw2l, g_w2l);

    const int n4 = Dd * Dd / 4;
    splitf<<<(n4 + 255) / 256, 256>>>((const float4*)Wq,   pwqh, pwql, n4);
    splitf<<<(n4 + 255) / 256, 256>>>((const float4*)Wk,   pwkh, pwkl, n4);
    splitf<<<(n4 + 255) / 256, 256>>>((const float4*)ff1w, pw1h, pw1l, n4);
    splitf<<<(n4 + 255) / 256, 256>>>((const float4*)ff2w, pw2h, pw2l, n4);

    ln_fused<<<NTOK, 256>>>(x, ln1s, ln1b, ln2s, ln2b);

    dim3 g0(Dd / 128, NTOK / 128);
    // q,k projections -> split bf16
    gemm3<3><<<g0, 256>>>(NTOK, Dd, Dd, phh, phl, pwqh, pwql,
                          nullptr, nullptr, nullptr, pqh, pql);
    gemm3<3><<<g0, 256>>>(NTOK, Dd, Dd, phh, phl, pwkh, pwkl,
                          nullptr, nullptr, nullptr, pkh, pkl);
    // FFN
    gemm3<1><<<g0, 256>>>(NTOK, Dd, Dd, ph2h, ph2l, pw1h, pw1l,
                          nullptr, ff1b, nullptr, pf1h, pf1l);
    gemm3<2><<<g0, 256>>>(NTOK, Dd, Dd, pf1h, pf1l, pw2h, pw2l,
                          out, ff2b, px2, nullptr, nullptr);

    // attention scores + softmax
    dim3 gs(Sq / 128, Sq / 128, NBH);
    scores_mma<<<gs, 256>>>(pqh, pql, pkh, pkl, attn);
    softmax_rows<<<NBH * Sq, 128>>>(attn);
}